// round 13
// baseline (speedup 1.0000x reference)
#include <cuda_runtime.h>
#include <math.h>
#include <stdint.h>

#define T_STEPS 512
#define BATCH   256
#define OBSD    256
#define HIDD    512
#define LSTMD   512
#define ACTD    32
#define ROWS    (T_STEPS * BATCH)   /* 131072 */
#define GATES_N (4 * LSTMD)         /* 2048 */
#define HT_ELEMS (BATCH * LSTMD)    /* 131072 */
#define NGRP     4
#define GRP_BLKS 32

// one extern-shared symbol for all dynamic-smem kernels
extern __shared__ char dynsmem[];

// ---------------- scratch (static device globals) ---------------------------
__device__ float    g_xr   [(size_t)ROWS * OBSD];
__device__ float    g_WencR[(size_t)OBSD * HIDD];
__device__ float    g_feats[(size_t)ROWS * HIDD];
__device__ float    g_gates[(size_t)ROWS * GATES_N];
__device__ float    g_ys   [(size_t)ROWS * LSTMD];
__device__ float    g_hT   [2 * HT_ELEMS];
__device__ float    g_WiP  [(size_t)HIDD * GATES_N];
__device__ unsigned g_WhP  [(size_t)LSTMD * GATES_N];
__device__ float    g_bP   [GATES_N];
__device__ float    g_Whd  [(size_t)LSTMD * 64];     // heads weights [k][64]
__device__ unsigned g_bar4 [NGRP * 32];

__device__ __forceinline__ float gelu_f(float x) {
    float x3 = x * x * x;
    float t  = tanhf(0.7978845608028654f * (x + 0.044715f * x3));
    return 0.5f * x * (1.0f + t);
}
__device__ __forceinline__ float sigm(float x) { return 1.0f / (1.0f + expf(-x)); }

__device__ __forceinline__ unsigned f2tf32(float x) {
    unsigned u;
    asm("cvt.rna.tf32.f32 %0, %1;" : "=r"(u) : "f"(x));
    return u;
}

__device__ __forceinline__ void mma_tf32(float c[4],
                                         unsigned a0, unsigned a1, unsigned a2, unsigned a3,
                                         unsigned b0, unsigned b1) {
    asm volatile(
        "mma.sync.aligned.m16n8k8.row.col.f32.tf32.tf32.f32 "
        "{%0,%1,%2,%3}, {%4,%5,%6,%7}, {%8,%9}, {%0,%1,%2,%3};\n"
        : "+f"(c[0]), "+f"(c[1]), "+f"(c[2]), "+f"(c[3])
        : "r"(a0), "r"(a1), "r"(a2), "r"(a3), "r"(b0), "r"(b1));
}

__device__ __forceinline__ void ldsm4(unsigned f[4], uint32_t addr) {
    asm volatile("ldmatrix.sync.aligned.m8n8.x4.shared.b16 {%0,%1,%2,%3}, [%4];"
                 : "=r"(f[0]), "=r"(f[1]), "=r"(f[2]), "=r"(f[3]) : "r"(addr));
}

__device__ __forceinline__ void cp16(void* smem_dst, const void* gsrc) {
    unsigned d = (unsigned)__cvta_generic_to_shared(smem_dst);
    asm volatile("cp.async.ca.shared.global [%0], [%1], 16;\n" :: "r"(d), "l"(gsrc));
}
__device__ __forceinline__ void cp_commit() {
    asm volatile("cp.async.commit_group;\n");
}
template <int N>
__device__ __forceinline__ void cp_wait() {
    asm volatile("cp.async.wait_group %0;\n" :: "n"(N));
}

// ---------------- small utility kernels -------------------------------------
__global__ void zero_kernel(float* p, int n) {
    int i = blockIdx.x * blockDim.x + threadIdx.x;
    if (i < n) p[i] = 0.0f;
}
__global__ void zero_bar4() {
    if (threadIdx.x < NGRP * 32) g_bar4[threadIdx.x] = 0u;
}

__global__ void round4_kernel(const float4* __restrict__ in,
                              float4* __restrict__ out, int n4) {
    int i = blockIdx.x * blockDim.x + threadIdx.x;
    if (i < n4) {
        float4 v = in[i];
        v.x = __uint_as_float(f2tf32(v.x));
        v.y = __uint_as_float(f2tf32(v.y));
        v.z = __uint_as_float(f2tf32(v.z));
        v.w = __uint_as_float(f2tf32(v.w));
        out[i] = v;
    }
}

__global__ void permute_wi(const float* __restrict__ W, float* __restrict__ Wp) {
    int idx = blockIdx.x * 256 + threadIdx.x;
    int k = idx >> 11, c = idx & 2047;
    Wp[idx] = __uint_as_float(f2tf32(W[(size_t)k * GATES_N + (c & 3) * LSTMD + (c >> 2)]));
}
__global__ void permute_wh(const float* __restrict__ W, unsigned* __restrict__ Wp) {
    int idx = blockIdx.x * 256 + threadIdx.x;
    int k = idx >> 11, c = idx & 2047;
    Wp[idx] = f2tf32(W[(size_t)k * GATES_N + (c & 3) * LSTMD + (c >> 2)]);
}
__global__ void permute_b(const float* __restrict__ b, float* __restrict__ bp) {
    int idx = blockIdx.x * 256 + threadIdx.x;
    if (idx < GATES_N) bp[idx] = b[(idx & 3) * LSTMD + (idx >> 2)];
}
// Whd[k][n]: n<32 -> W_mu[k][n]; n==32 -> W_v[k]; else 0   (tf32-rounded)
__global__ void prep_whd(const float* __restrict__ Wmu,
                         const float* __restrict__ Wv,
                         float* __restrict__ Whd) {
    int idx = blockIdx.x * 256 + threadIdx.x;     // < 512*64
    int k = idx >> 6, n = idx & 63;
    float v = 0.0f;
    if (n < 32)       v = Wmu[k * ACTD + n];
    else if (n == 32) v = Wv[k];
    Whd[idx] = __uint_as_float(f2tf32(v));
}

// ---------------- big GEMM (unchanged): cp.async double-buffered ------------
#define GA_STRIDE 36
#define GB_STRIDE 136
#define GA_ELEMS  (128 * GA_STRIDE)
#define GB_ELEMS  (32 * GB_STRIDE)
#define SMEM_GEMM ((2 * GA_ELEMS + 2 * GB_ELEMS) * 4)

__global__ void __launch_bounds__(256)
gemm_mma(const float* __restrict__ A,
         const float* __restrict__ B,
         const float* __restrict__ bias,
         float* __restrict__ C,
         int M, int N, int K, int do_gelu, int do_round)
{
    unsigned* gsm = (unsigned*)dynsmem;
    unsigned* As = gsm;
    unsigned* Bs = gsm + 2 * GA_ELEMS;

    const int bm = blockIdx.y * 128;
    const int bn = blockIdx.x * 128;
    const int tid  = threadIdx.x;
    const int warp = tid >> 5;
    const int lane = tid & 31;
    const int wm = (warp & 1) * 64;
    const int wn = (warp >> 1) * 32;
    const int r  = lane >> 2;
    const int q  = lane & 3;

    float acc[4][4][4];
#pragma unroll
    for (int mt = 0; mt < 4; mt++)
#pragma unroll
        for (int nt = 0; nt < 4; nt++)
#pragma unroll
            for (int i = 0; i < 4; i++) acc[mt][nt][i] = 0.0f;

    const float* Ab = A + (size_t)bm * K;
    const int nK = K >> 5;

    auto load_stage = [&](int kt, int buf) {
        unsigned* Ad = As + buf * GA_ELEMS;
        unsigned* Bd = Bs + buf * GB_ELEMS;
        int k0 = kt * 32;
#pragma unroll
        for (int it = 0; it < 4; it++) {
            int i  = tid + it * 256;
            int m  = i >> 3;
            int kq = (i & 7) * 4;
            cp16(&Ad[m * GA_STRIDE + kq], Ab + (size_t)m * K + k0 + kq);
        }
#pragma unroll
        for (int it = 0; it < 4; it++) {
            int i  = tid + it * 256;
            int kr = i >> 5;
            int nq = (i & 31) * 4;
            cp16(&Bd[kr * GB_STRIDE + nq], B + (size_t)(k0 + kr) * N + bn + nq);
        }
        cp_commit();
    };

    load_stage(0, 0);

    for (int kt = 0; kt < nK; kt++) {
        if (kt + 1 < nK) { load_stage(kt + 1, (kt + 1) & 1); cp_wait<1>(); }
        else             { cp_wait<0>(); }
        __syncthreads();

        const unsigned* Ac = As + (kt & 1) * GA_ELEMS;
        const unsigned* Bc = Bs + (kt & 1) * GB_ELEMS;
#pragma unroll
        for (int kk = 0; kk < 32; kk += 8) {
            unsigned af[4][4], bf[4][2];
#pragma unroll
            for (int mt = 0; mt < 4; mt++) {
                int mb = wm + mt * 16;
                af[mt][0] = Ac[(mb + r    ) * GA_STRIDE + kk + q];
                af[mt][1] = Ac[(mb + r + 8) * GA_STRIDE + kk + q];
                af[mt][2] = Ac[(mb + r    ) * GA_STRIDE + kk + q + 4];
                af[mt][3] = Ac[(mb + r + 8) * GA_STRIDE + kk + q + 4];
            }
#pragma unroll
            for (int nt = 0; nt < 4; nt++) {
                int nb = wn + nt * 8 + r;
                bf[nt][0] = Bc[(kk + q    ) * GB_STRIDE + nb];
                bf[nt][1] = Bc[(kk + q + 4) * GB_STRIDE + nb];
            }
#pragma unroll
            for (int mt = 0; mt < 4; mt++)
#pragma unroll
                for (int nt = 0; nt < 4; nt++)
                    mma_tf32(acc[mt][nt], af[mt][0], af[mt][1], af[mt][2], af[mt][3],
                             bf[nt][0], bf[nt][1]);
        }
        __syncthreads();
    }

#pragma unroll
    for (int mt = 0; mt < 4; mt++) {
#pragma unroll
        for (int nt = 0; nt < 4; nt++) {
            int row = bm + wm + mt * 16 + r;
            int col = bn + wn + nt * 8 + 2 * q;
            float b0 = bias[col], b1 = bias[col + 1];
            float z00 = acc[mt][nt][0] + b0, z01 = acc[mt][nt][1] + b1;
            float z10 = acc[mt][nt][2] + b0, z11 = acc[mt][nt][3] + b1;
            if (do_gelu) {
                z00 = gelu_f(z00); z01 = gelu_f(z01);
                z10 = gelu_f(z10); z11 = gelu_f(z11);
            }
            if (do_round) {
                z00 = __uint_as_float(f2tf32(z00));
                z01 = __uint_as_float(f2tf32(z01));
                z10 = __uint_as_float(f2tf32(z10));
                z11 = __uint_as_float(f2tf32(z11));
            }
            *reinterpret_cast<float2*>(C + (size_t)row * N + col) =
                make_float2(z00, z01);
            *reinterpret_cast<float2*>(C + (size_t)(row + 8) * N + col) =
                make_float2(z10, z11);
        }
    }
}

// ---------------- persistent fused LSTM recurrence --------------------------
// 128 blocks (32 j x 4 b). BK=128: 4 chunks/step, 7 syncs/step.
// W_h transposed in smem [n][k] (ldmatrix B frags), h tile [m][k] (A frags),
// per-batch-group barrier.
#define WT_STRIDE 516                           /* 512 + 4 */
#define WT_ELEMS  (64 * WT_STRIDE)              /* 33024 u32 */
#define AS_STRIDE 132                           /* 128 + 4; 528B row, 16B-aligned */
#define AS_ELEMS  (64 * AS_STRIDE)              /* 8448 u32 per buf */
#define CS_STRIDE 17
#define SMEM_LSTM ((WT_ELEMS + 2 * AS_ELEMS + 64 * CS_STRIDE) * 4)

__global__ void __launch_bounds__(256, 1)
lstm_persistent(const unsigned* __restrict__ Wp,
                const float* __restrict__ gates,
                float* __restrict__ ys)
{
    unsigned* smem = (unsigned*)dynsmem;
    unsigned* Wst = smem;                               // [64][516]  (n, k)
    unsigned* As0 = smem + WT_ELEMS;                    // [2][64][132] (m, k)
    float*    Cs  = (float*)(smem + WT_ELEMS + 2 * AS_ELEMS);  // [64][17]

    const int jt = blockIdx.x;
    const int bt = blockIdx.y;
    const int bn = jt * 64;
    const int bm = bt * 64;
    const int tid  = threadIdx.x;
    const int warp = tid >> 5;
    const int lane = tid & 31;
    const int wm = (warp & 1) * 32;
    const int wn = (warp >> 1) * 16;
    const int r  = lane >> 2;
    const int q  = lane & 3;
    const int p  = q & 1;
    unsigned* mybar = &g_bar4[bt * 32];

    // W tile transposed into smem once: Wst[n][k] = Wp[k][bn+n]
    for (int i = tid; i < 64 * LSTMD; i += 256) {
        int n = i & 63, k = i >> 6;
        Wst[n * WT_STRIDE + k] = Wp[(size_t)k * GATES_N + bn + n];
    }
    for (int i = tid; i < 64 * CS_STRIDE; i += 256) Cs[i] = 0.0f;
    __syncthreads();

    // ldmatrix lane-address precompute (byte addresses in shared space)
    const uint32_t smem_u32 = (uint32_t)__cvta_generic_to_shared(dynsmem);
    const uint32_t as_base  = smem_u32 + WT_ELEMS * 4;
    uint32_t a_rel[2];
#pragma unroll
    for (int mt = 0; mt < 2; mt++)
        a_rel[mt] = (uint32_t)(((wm + mt * 16 + (lane & 15)) * AS_STRIDE
                                + ((lane >> 4) << 2)) * 4);
    const uint32_t b_base = smem_u32 +
        (uint32_t)((((wn + ((lane >> 4) << 3) + (lane & 7)) * WT_STRIDE)
                    + (((lane >> 3) & 1) << 2)) * 4);

    for (int t = 0; t < T_STEPS; t++) {
        const float* hin  = g_hT + ((t & 1) ? HT_ELEMS : 0);
        float*       hout = g_hT + ((t & 1) ? 0 : HT_ELEMS);
        const float* gx   = gates + (size_t)t * BATCH * GATES_N;

        float2 gxr[2][2][2];
#pragma unroll
        for (int mt = 0; mt < 2; mt++)
#pragma unroll
            for (int nt = 0; nt < 2; nt++) {
                int row = bm + wm + mt * 16 + r;
                int col = bn + wn + nt * 8 + 2 * q;
                gxr[mt][nt][0] = *reinterpret_cast<const float2*>(
                    gx + (size_t)row * GATES_N + col);
                gxr[mt][nt][1] = *reinterpret_cast<const float2*>(
                    gx + (size_t)(row + 8) * GATES_N + col);
            }

        float acc[2][2][4];
#pragma unroll
        for (int mt = 0; mt < 2; mt++)
#pragma unroll
            for (int nt = 0; nt < 2; nt++)
#pragma unroll
                for (int i = 0; i < 4; i++) acc[mt][nt][i] = 0.0f;

        // prefetch chunk 0 (64 rows x 128 k)
        {
            unsigned* A = As0;
#pragma unroll
            for (int it = 0; it < 8; it++) {
                int i  = tid + it * 256;
                int m  = i >> 5;
                int kq = (i & 31) * 4;
                cp16(&A[m * AS_STRIDE + kq], hin + (size_t)(bm + m) * LSTMD + kq);
            }
            cp_commit();
        }

        for (int c = 0; c < 4; c++) {
            if (c < 3) {
                unsigned* A = As0 + ((c + 1) & 1) * AS_ELEMS;
                int kb = (c + 1) * 128;
#pragma unroll
                for (int it = 0; it < 8; it++) {
                    int i  = tid + it * 256;
                    int m  = i >> 5;
                    int kq = (i & 31) * 4;
                    cp16(&A[m * AS_STRIDE + kq],
                         hin + (size_t)(bm + m) * LSTMD + kb + kq);
                }
                cp_commit();
                cp_wait<1>();
            } else {
                cp_wait<0>();
            }
            __syncthreads();

            const uint32_t abuf  = as_base + (uint32_t)((c & 1) * AS_ELEMS * 4);
            const int      kbase = c * 128;
#pragma unroll
            for (int kk = 0; kk < 128; kk += 8) {
                unsigned af0[4], af1[4], bf[4];
                ldsm4(af0, abuf + a_rel[0] + kk * 4);
                ldsm4(af1, abuf + a_rel[1] + kk * 4);
                ldsm4(bf,  b_base + (uint32_t)((kbase + kk) * 4));
                mma_tf32(acc[0][0], af0[0], af0[1], af0[2], af0[3], bf[0], bf[1]);
                mma_tf32(acc[0][1], af0[0], af0[1], af0[2], af0[3], bf[2], bf[3]);
                mma_tf32(acc[1][0], af1[0], af1[1], af1[2], af1[3], bf[0], bf[1]);
                mma_tf32(acc[1][1], af1[0], af1[1], af1[2], af1[3], bf[2], bf[3]);
            }
            if (c < 3) __syncthreads();   // last chunk: group barrier sync suffices
        }

        float* yst = ys + (size_t)t * BATCH * LSTMD;
#pragma unroll
        for (int mt = 0; mt < 2; mt++) {
#pragma unroll
            for (int nt = 0; nt < 2; nt++) {
                int lrow = wm + mt * 16 + r;
                int lcol = wn + nt * 8 + 2 * q;
                float z00 = acc[mt][nt][0] + gxr[mt][nt][0].x;
                float z01 = acc[mt][nt][1] + gxr[mt][nt][0].y;
                float z10 = acc[mt][nt][2] + gxr[mt][nt][1].x;
                float z11 = acc[mt][nt][3] + gxr[mt][nt][1].y;

                float u0a = (p == 0) ? sigm(z00) : tanhf(z00);
                float u1a = sigm(z01);
                float u0b = (p == 0) ? sigm(z10) : tanhf(z10);
                float u1b = sigm(z11);

                float v0a = __shfl_xor_sync(0xffffffffu, u0a, 1);
                float v1a = __shfl_xor_sync(0xffffffffu, u1a, 1);
                float v0b = __shfl_xor_sync(0xffffffffu, u0b, 1);
                float v1b = __shfl_xor_sync(0xffffffffu, u1b, 1);

                if (p == 0) {
                    int jl = lcol >> 2;
                    int jg = jt * 16 + jl;
                    {
                        float co = Cs[lrow * CS_STRIDE + jl];
                        float cn = u1a * co + u0a * v0a;
                        Cs[lrow * CS_STRIDE + jl] = cn;
                        float h = v1a * tanhf(cn);
                        size_t gi = (size_t)(bm + lrow) * LSTMD + jg;
                        yst[gi]  = h;
                        hout[gi] = __uint_as_float(f2tf32(h));
                    }
                    {
                        int lr2 = lrow + 8;
                        float co = Cs[lr2 * CS_STRIDE + jl];
                        float cn = u1b * co + u0b * v0b;
                        Cs[lr2 * CS_STRIDE + jl] = cn;
                        float h = v1b * tanhf(cn);
                        size_t gi = (size_t)(bm + lr2) * LSTMD + jg;
                        yst[gi]  = h;
                        hout[gi] = __uint_as_float(f2tf32(h));
                    }
                }
            }
        }

        if (t + 1 < T_STEPS) {
            __syncthreads();
            if (tid == 0) {
                __threadfence();
                atomicAdd(mybar, 1u);
                unsigned tgt = (unsigned)(t + 1) * GRP_BLKS;
                unsigned v;
                for (;;) {
                    asm volatile("ld.acquire.gpu.u32 %0, [%1];"
                                 : "=r"(v) : "l"(mybar) : "memory");
                    if (v >= tgt) break;
                    __nanosleep(32);
                }
            }
            __syncthreads();
        }
    }
}

// ---------------- heads as tf32 mma GEMM (unchanged) ------------------------
__global__ void __launch_bounds__(256)
heads_mma(const float* __restrict__ Whd,    // [512][64] tf32-rounded
          const float* __restrict__ bmu,
          const float* __restrict__ logstd,
          const float* __restrict__ bv,
          float* __restrict__ out)
{
    __shared__ unsigned As[128][36];
    __shared__ unsigned Bs[32][72];

    const int bm = blockIdx.x * 128;
    const int tid  = threadIdx.x;
    const int warp = tid >> 5;
    const int lane = tid & 31;
    const int wm = (warp & 1) * 64;
    const int wn = (warp >> 1) * 16;
    const int r  = lane >> 2;
    const int q  = lane & 3;

    float acc[4][2][4];
#pragma unroll
    for (int mt = 0; mt < 4; mt++)
#pragma unroll
        for (int nt = 0; nt < 2; nt++)
#pragma unroll
            for (int i = 0; i < 4; i++) acc[mt][nt][i] = 0.0f;

    const float* Ab = g_ys + (size_t)bm * LSTMD;

    for (int k0 = 0; k0 < LSTMD; k0 += 32) {
#pragma unroll
        for (int it = 0; it < 4; it++) {             // A 128x32, cvt to tf32
            int i  = tid + it * 256;
            int m  = i >> 3;
            int kq = (i & 7) * 4;
            float4 v = *reinterpret_cast<const float4*>(
                Ab + (size_t)m * LSTMD + k0 + kq);
            unsigned* d = &As[m][kq];
            d[0] = f2tf32(v.x); d[1] = f2tf32(v.y);
            d[2] = f2tf32(v.z); d[3] = f2tf32(v.w);
        }
#pragma unroll
        for (int it = 0; it < 2; it++) {             // B 32x64 (already rounded)
            int i  = tid + it * 256;
            int kr = i >> 4;
            int nq = (i & 15) * 4;
            uint4 v = *reinterpret_cast<const uint4*>(
                Whd + (size_t)(k0 + kr) * 64 + nq);
            *reinterpret_cast<uint4*>(&Bs[kr][nq]) = v;
        }
        __syncthreads();

#pragma unroll
        for (int kk = 0; kk < 32; kk += 8) {
            unsigned af[4][4], bf[2][2];
#pragma unroll
            for (int mt = 0; mt < 4; mt++) {
                int mb = wm + mt * 16;
                af[mt][0] = As[mb + r    ][kk + q];
                af[mt][1] = As[mb + r + 8][kk + q];
                af[mt][2] = As[mb + r    ][kk + q + 4];
                af[mt][3] = As[mb + r + 8][kk + q + 4];
            }
#pragma unroll
            for (int nt = 0; nt < 2; nt++) {
                int nb = wn + nt * 8 + r;
                bf[nt][0] = Bs[kk + q    ][nb];
                bf[nt][1] = Bs[kk + q + 4][nb];
            }
#pragma unroll
            for (int mt = 0; mt < 4; mt++)
#pragma unroll
                for (int nt = 0; nt < 2; nt++)
                    mma_tf32(acc[mt][nt], af[mt][0], af[mt][1], af[mt][2], af[mt][3],
                             bf[nt][0], bf[nt][1]);
        }
        __syncthreads();
    }

    float* mu    = out;
    float* sigma = out + (size_t)ROWS * ACTD;
    float* value = out + (size_t)2 * ROWS * ACTD;

#pragma unroll
    for (int mt = 0; mt < 4; mt++) {
#pragma unroll
        for (int nt = 0; nt < 2; nt++) {
            int row = bm + wm + mt * 16 + r;
            int col = wn + nt * 8 + 2 * q;
            if (col < 32) {
                float b0 = bmu[col], b1 = bmu[col + 1];
                float s0 = expf(logstd[col]), s1 = expf(logstd[col + 1]);
                mu[(size_t)row * ACTD + col]           = acc[mt][nt][0] + b0;
                mu[(size_t)row * ACTD + col + 1]       = acc[mt][nt][1] + b1;
                mu[(size_t)(row + 8) * ACTD + col]     = acc[mt][nt][2] + b0;
                mu[(size_t)(row + 8) * ACTD + col + 1] = acc[mt][nt][3] + b1;
                sigma[(size_t)row * ACTD + col]           = s0;
                sigma[(size_t)row * ACTD + col + 1]       = s1;
                sigma[(size_t)(row + 8) * ACTD + col]     = s0;
                sigma[(size_t)(row + 8) * ACTD + col + 1] = s1;
            } else if (col == 32) {
                value[row]     = acc[mt][nt][0] + bv[0];
                value[row + 8] = acc[mt][nt][2] + bv[0];
            }
        }
    }
}

// ---------------- launch ----------------------------------------------------
extern "C" void kernel_launch(void* const* d_in, const int* in_sizes, int n_in,
                              void* d_out, int out_size)
{
    (void)in_sizes; (void)n_in; (void)out_size;
    const float* x      = (const float*)d_in[0];
    const float* W_enc  = (const float*)d_in[1];
    const float* b_enc  = (const float*)d_in[2];
    const float* W_i    = (const float*)d_in[3];
    const float* W_h    = (const float*)d_in[4];
    const float* b_lstm = (const float*)d_in[5];
    const float* W_mu   = (const float*)d_in[6];
    const float* b_mu   = (const float*)d_in[7];
    const float* logstd = (const float*)d_in[8];
    const float* W_v    = (const float*)d_in[9];
    const float* b_v    = (const float*)d_in[10];
    float* out = (float*)d_out;

    float *xr, *WencR, *feats, *gates, *ys, *hT, *WiP, *bP, *Whd;
    unsigned* WhP;
    cudaGetSymbolAddress((void**)&xr,    g_xr);
    cudaGetSymbolAddress((void**)&WencR, g_WencR);
    cudaGetSymbolAddress((void**)&feats, g_feats);
    cudaGetSymbolAddress((void**)&gates, g_gates);
    cudaGetSymbolAddress((void**)&ys,    g_ys);
    cudaGetSymbolAddress((void**)&hT,    g_hT);
    cudaGetSymbolAddress((void**)&WiP,   g_WiP);
    cudaGetSymbolAddress((void**)&WhP,   g_WhP);
    cudaGetSymbolAddress((void**)&bP,    g_bP);
    cudaGetSymbolAddress((void**)&Whd,   g_Whd);

    static int attr_set = 0;
    if (!attr_set) {
        cudaFuncSetAttribute(lstm_persistent,
                             cudaFuncAttributeMaxDynamicSharedMemorySize, SMEM_LSTM);
        cudaFuncSetAttribute(gemm_mma,
                             cudaFuncAttributeMaxDynamicSharedMemorySize, SMEM_GEMM);
        attr_set = 1;
    }

    zero_kernel<<<(HT_ELEMS + 255) / 256, 256>>>(hT, HT_ELEMS);
    zero_bar4<<<1, 128>>>();

    round4_kernel<<<(ROWS * OBSD / 4 + 255) / 256, 256>>>(
        (const float4*)x, (float4*)xr, ROWS * OBSD / 4);
    round4_kernel<<<(OBSD * HIDD / 4 + 255) / 256, 256>>>(
        (const float4*)W_enc, (float4*)WencR, OBSD * HIDD / 4);
    permute_wi<<<(HIDD * GATES_N) / 256, 256>>>(W_i, WiP);
    permute_wh<<<(LSTMD * GATES_N) / 256, 256>>>(W_h, WhP);
    permute_b<<<(GATES_N + 255) / 256, 256>>>(b_lstm, bP);
    prep_whd<<<(LSTMD * 64) / 256, 256>>>(W_mu, W_v, Whd);

    {
        dim3 grid(HIDD / 128, ROWS / 128);
        gemm_mma<<<grid, 256, SMEM_GEMM>>>(xr, WencR, b_enc, feats,
                                           ROWS, HIDD, OBSD, 1, 1);
    }
    {
        dim3 grid(GATES_N / 128, ROWS / 128);
        gemm_mma<<<grid, 256, SMEM_GEMM>>>(feats, WiP, bP, gates,
                                           ROWS, GATES_N, HIDD, 0, 0);
    }
    {
        dim3 grid(32, 4);
        lstm_persistent<<<grid, 256, SMEM_LSTM>>>(WhP, gates, ys);
    }
    heads_mma<<<ROWS / 128, 256>>>(Whd, b_mu, logstd, b_v, out);
}

// round 14
// speedup vs baseline: 1.0511x; 1.0511x over previous
#include <cuda_runtime.h>
#include <math.h>
#include <stdint.h>

#define T_STEPS 512
#define BATCH   256
#define OBSD    256
#define HIDD    512
#define LSTMD   512
#define ACTD    32
#define ROWS    (T_STEPS * BATCH)   /* 131072 */
#define GATES_N (4 * LSTMD)         /* 2048 */
#define HT_ELEMS (BATCH * LSTMD)    /* 131072 */
#define NGRP     4
#define GRP_BLKS 32

// one extern-shared symbol for all dynamic-smem kernels
extern __shared__ char dynsmem[];

// ---------------- scratch (static device globals) ---------------------------
__device__ float    g_xr   [(size_t)ROWS * OBSD];
__device__ float    g_WencR[(size_t)OBSD * HIDD];
__device__ float    g_feats[(size_t)ROWS * HIDD];
__device__ float    g_gates[(size_t)ROWS * GATES_N];
__device__ float    g_ys   [(size_t)ROWS * LSTMD];
__device__ float    g_hT   [2 * HT_ELEMS];
__device__ float    g_WiP  [(size_t)HIDD * GATES_N];
__device__ unsigned g_WhP  [(size_t)LSTMD * GATES_N];
__device__ float    g_bP   [GATES_N];
__device__ float    g_Whd  [(size_t)LSTMD * 64];     // heads weights [k][64]
__device__ unsigned g_bar4 [NGRP * 32];

// fast transcendentals: ~1e-6 rel error (ex2.approx + rcp.approx based)
__device__ __forceinline__ float fast_tanh(float x) {
    float e = __expf(2.0f * x);
    return 1.0f - __fdividef(2.0f, e + 1.0f);
}
__device__ __forceinline__ float fast_sigm(float x) {
    return __fdividef(1.0f, 1.0f + __expf(-x));
}
__device__ __forceinline__ float gelu_f(float x) {
    float x3 = x * x * x;
    float t  = fast_tanh(0.7978845608028654f * (x + 0.044715f * x3));
    return 0.5f * x * (1.0f + t);
}

__device__ __forceinline__ unsigned f2tf32(float x) {
    unsigned u;
    asm("cvt.rna.tf32.f32 %0, %1;" : "=r"(u) : "f"(x));
    return u;
}

__device__ __forceinline__ void mma_tf32(float c[4],
                                         unsigned a0, unsigned a1, unsigned a2, unsigned a3,
                                         unsigned b0, unsigned b1) {
    asm volatile(
        "mma.sync.aligned.m16n8k8.row.col.f32.tf32.tf32.f32 "
        "{%0,%1,%2,%3}, {%4,%5,%6,%7}, {%8,%9}, {%0,%1,%2,%3};\n"
        : "+f"(c[0]), "+f"(c[1]), "+f"(c[2]), "+f"(c[3])
        : "r"(a0), "r"(a1), "r"(a2), "r"(a3), "r"(b0), "r"(b1));
}

__device__ __forceinline__ void ldsm4(unsigned f[4], uint32_t addr) {
    asm volatile("ldmatrix.sync.aligned.m8n8.x4.shared.b16 {%0,%1,%2,%3}, [%4];"
                 : "=r"(f[0]), "=r"(f[1]), "=r"(f[2]), "=r"(f[3]) : "r"(addr));
}

__device__ __forceinline__ void cp16(void* smem_dst, const void* gsrc) {
    unsigned d = (unsigned)__cvta_generic_to_shared(smem_dst);
    asm volatile("cp.async.ca.shared.global [%0], [%1], 16;\n" :: "r"(d), "l"(gsrc));
}
__device__ __forceinline__ void cp_commit() {
    asm volatile("cp.async.commit_group;\n");
}
template <int N>
__device__ __forceinline__ void cp_wait() {
    asm volatile("cp.async.wait_group %0;\n" :: "n"(N));
}

// ---------------- small utility kernels -------------------------------------
__global__ void zero_kernel(float* p, int n) {
    int i = blockIdx.x * blockDim.x + threadIdx.x;
    if (i < n) p[i] = 0.0f;
}
__global__ void zero_bar4() {
    if (threadIdx.x < NGRP * 32) g_bar4[threadIdx.x] = 0u;
}

__global__ void round4_kernel(const float4* __restrict__ in,
                              float4* __restrict__ out, int n4) {
    int i = blockIdx.x * blockDim.x + threadIdx.x;
    if (i < n4) {
        float4 v = in[i];
        v.x = __uint_as_float(f2tf32(v.x));
        v.y = __uint_as_float(f2tf32(v.y));
        v.z = __uint_as_float(f2tf32(v.z));
        v.w = __uint_as_float(f2tf32(v.w));
        out[i] = v;
    }
}

__global__ void permute_wi(const float* __restrict__ W, float* __restrict__ Wp) {
    int idx = blockIdx.x * 256 + threadIdx.x;
    int k = idx >> 11, c = idx & 2047;
    Wp[idx] = __uint_as_float(f2tf32(W[(size_t)k * GATES_N + (c & 3) * LSTMD + (c >> 2)]));
}
__global__ void permute_wh(const float* __restrict__ W, unsigned* __restrict__ Wp) {
    int idx = blockIdx.x * 256 + threadIdx.x;
    int k = idx >> 11, c = idx & 2047;
    Wp[idx] = f2tf32(W[(size_t)k * GATES_N + (c & 3) * LSTMD + (c >> 2)]);
}
__global__ void permute_b(const float* __restrict__ b, float* __restrict__ bp) {
    int idx = blockIdx.x * 256 + threadIdx.x;
    if (idx < GATES_N) bp[idx] = b[(idx & 3) * LSTMD + (idx >> 2)];
}
// Whd[k][n]: n<32 -> W_mu[k][n]; n==32 -> W_v[k]; else 0   (tf32-rounded)
__global__ void prep_whd(const float* __restrict__ Wmu,
                         const float* __restrict__ Wv,
                         float* __restrict__ Whd) {
    int idx = blockIdx.x * 256 + threadIdx.x;     // < 512*64
    int k = idx >> 6, n = idx & 63;
    float v = 0.0f;
    if (n < 32)       v = Wmu[k * ACTD + n];
    else if (n == 32) v = Wv[k];
    Whd[idx] = __uint_as_float(f2tf32(v));
}

// ---------------- big GEMM: cp.async double-buffered ------------------------
#define GA_STRIDE 36
#define GB_STRIDE 136
#define GA_ELEMS  (128 * GA_STRIDE)
#define GB_ELEMS  (32 * GB_STRIDE)
#define SMEM_GEMM ((2 * GA_ELEMS + 2 * GB_ELEMS) * 4)

__global__ void __launch_bounds__(256)
gemm_mma(const float* __restrict__ A,
         const float* __restrict__ B,
         const float* __restrict__ bias,
         float* __restrict__ C,
         int M, int N, int K, int do_gelu, int do_round)
{
    unsigned* gsm = (unsigned*)dynsmem;
    unsigned* As = gsm;
    unsigned* Bs = gsm + 2 * GA_ELEMS;

    const int bm = blockIdx.y * 128;
    const int bn = blockIdx.x * 128;
    const int tid  = threadIdx.x;
    const int warp = tid >> 5;
    const int lane = tid & 31;
    const int wm = (warp & 1) * 64;
    const int wn = (warp >> 1) * 32;
    const int r  = lane >> 2;
    const int q  = lane & 3;

    float acc[4][4][4];
#pragma unroll
    for (int mt = 0; mt < 4; mt++)
#pragma unroll
        for (int nt = 0; nt < 4; nt++)
#pragma unroll
            for (int i = 0; i < 4; i++) acc[mt][nt][i] = 0.0f;

    const float* Ab = A + (size_t)bm * K;
    const int nK = K >> 5;

    auto load_stage = [&](int kt, int buf) {
        unsigned* Ad = As + buf * GA_ELEMS;
        unsigned* Bd = Bs + buf * GB_ELEMS;
        int k0 = kt * 32;
#pragma unroll
        for (int it = 0; it < 4; it++) {
            int i  = tid + it * 256;
            int m  = i >> 3;
            int kq = (i & 7) * 4;
            cp16(&Ad[m * GA_STRIDE + kq], Ab + (size_t)m * K + k0 + kq);
        }
#pragma unroll
        for (int it = 0; it < 4; it++) {
            int i  = tid + it * 256;
            int kr = i >> 5;
            int nq = (i & 31) * 4;
            cp16(&Bd[kr * GB_STRIDE + nq], B + (size_t)(k0 + kr) * N + bn + nq);
        }
        cp_commit();
    };

    load_stage(0, 0);

    for (int kt = 0; kt < nK; kt++) {
        if (kt + 1 < nK) { load_stage(kt + 1, (kt + 1) & 1); cp_wait<1>(); }
        else             { cp_wait<0>(); }
        __syncthreads();

        const unsigned* Ac = As + (kt & 1) * GA_ELEMS;
        const unsigned* Bc = Bs + (kt & 1) * GB_ELEMS;
#pragma unroll
        for (int kk = 0; kk < 32; kk += 8) {
            unsigned af[4][4], bf[4][2];
#pragma unroll
            for (int mt = 0; mt < 4; mt++) {
                int mb = wm + mt * 16;
                af[mt][0] = Ac[(mb + r    ) * GA_STRIDE + kk + q];
                af[mt][1] = Ac[(mb + r + 8) * GA_STRIDE + kk + q];
                af[mt][2] = Ac[(mb + r    ) * GA_STRIDE + kk + q + 4];
                af[mt][3] = Ac[(mb + r + 8) * GA_STRIDE + kk + q + 4];
            }
#pragma unroll
            for (int nt = 0; nt < 4; nt++) {
                int nb = wn + nt * 8 + r;
                bf[nt][0] = Bc[(kk + q    ) * GB_STRIDE + nb];
                bf[nt][1] = Bc[(kk + q + 4) * GB_STRIDE + nb];
            }
#pragma unroll
            for (int mt = 0; mt < 4; mt++)
#pragma unroll
                for (int nt = 0; nt < 4; nt++)
                    mma_tf32(acc[mt][nt], af[mt][0], af[mt][1], af[mt][2], af[mt][3],
                             bf[nt][0], bf[nt][1]);
        }
        __syncthreads();
    }

#pragma unroll
    for (int mt = 0; mt < 4; mt++) {
#pragma unroll
        for (int nt = 0; nt < 4; nt++) {
            int row = bm + wm + mt * 16 + r;
            int col = bn + wn + nt * 8 + 2 * q;
            float b0 = bias[col], b1 = bias[col + 1];
            float z00 = acc[mt][nt][0] + b0, z01 = acc[mt][nt][1] + b1;
            float z10 = acc[mt][nt][2] + b0, z11 = acc[mt][nt][3] + b1;
            if (do_gelu) {
                z00 = gelu_f(z00); z01 = gelu_f(z01);
                z10 = gelu_f(z10); z11 = gelu_f(z11);
            }
            if (do_round) {
                z00 = __uint_as_float(f2tf32(z00));
                z01 = __uint_as_float(f2tf32(z01));
                z10 = __uint_as_float(f2tf32(z10));
                z11 = __uint_as_float(f2tf32(z11));
            }
            *reinterpret_cast<float2*>(C + (size_t)row * N + col) =
                make_float2(z00, z01);
            *reinterpret_cast<float2*>(C + (size_t)(row + 8) * N + col) =
                make_float2(z10, z11);
        }
    }
}

// ---------------- persistent fused LSTM recurrence (R12 base) ---------------
// 128 blocks (32 j x 4 b), BK=64, ldmatrix k-loop, per-batch-group barrier.
// NEW: gx for step t+1 prefetched into registers during step t's mma.
#define WT_STRIDE 516                           /* 512 + 4 */
#define WT_ELEMS  (64 * WT_STRIDE)              /* 33024 u32 */
#define AS_STRIDE 68                            /* 272B row */
#define AS_ELEMS  (64 * AS_STRIDE)              /* 4352 u32 per buf */
#define CS_STRIDE 17
#define SMEM_LSTM ((WT_ELEMS + 2 * AS_ELEMS + 64 * CS_STRIDE) * 4)

__global__ void __launch_bounds__(256, 1)
lstm_persistent(const unsigned* __restrict__ Wp,
                const float* __restrict__ gates,
                float* __restrict__ ys)
{
    unsigned* smem = (unsigned*)dynsmem;
    unsigned* Wst = smem;                               // [64][516]  (n, k)
    unsigned* As0 = smem + WT_ELEMS;                    // [2][64][68] (m, k)
    float*    Cs  = (float*)(smem + WT_ELEMS + 2 * AS_ELEMS);  // [64][17]

    const int jt = blockIdx.x;
    const int bt = blockIdx.y;
    const int bn = jt * 64;
    const int bm = bt * 64;
    const int tid  = threadIdx.x;
    const int warp = tid >> 5;
    const int lane = tid & 31;
    const int wm = (warp & 1) * 32;
    const int wn = (warp >> 1) * 16;
    const int r  = lane >> 2;
    const int q  = lane & 3;
    const int p  = q & 1;
    unsigned* mybar = &g_bar4[bt * 32];

    // W tile transposed into smem once: Wst[n][k] = Wp[k][bn+n]
    for (int i = tid; i < 64 * LSTMD; i += 256) {
        int n = i & 63, k = i >> 6;
        Wst[n * WT_STRIDE + k] = Wp[(size_t)k * GATES_N + bn + n];
    }
    for (int i = tid; i < 64 * CS_STRIDE; i += 256) Cs[i] = 0.0f;
    __syncthreads();

    // ldmatrix lane-address precompute
    const uint32_t smem_u32 = (uint32_t)__cvta_generic_to_shared(dynsmem);
    const uint32_t as_base  = smem_u32 + WT_ELEMS * 4;
    uint32_t a_rel[2];
#pragma unroll
    for (int mt = 0; mt < 2; mt++)
        a_rel[mt] = (uint32_t)(((wm + mt * 16 + (lane & 15)) * AS_STRIDE
                                + ((lane >> 4) << 2)) * 4);
    const uint32_t b_base = smem_u32 +
        (uint32_t)((((wn + ((lane >> 4) << 3) + (lane & 7)) * WT_STRIDE)
                    + (((lane >> 3) & 1) << 2)) * 4);

    // gx row/col (per thread) for prefetching
    const int gx_row0 = bm + wm + r;
    const int gx_col0 = bn + wn + 2 * q;

    // preload gx for t=0
    float2 gxc[2][2][2];
#pragma unroll
    for (int mt = 0; mt < 2; mt++)
#pragma unroll
        for (int nt = 0; nt < 2; nt++) {
            int row = gx_row0 + mt * 16;
            int col = gx_col0 + nt * 8;
            gxc[mt][nt][0] = *reinterpret_cast<const float2*>(
                gates + (size_t)row * GATES_N + col);
            gxc[mt][nt][1] = *reinterpret_cast<const float2*>(
                gates + (size_t)(row + 8) * GATES_N + col);
        }

    for (int t = 0; t < T_STEPS; t++) {
        const float* hin  = g_hT + ((t & 1) ? HT_ELEMS : 0);
        float*       hout = g_hT + ((t & 1) ? 0 : HT_ELEMS);

        float acc[2][2][4];
#pragma unroll
        for (int mt = 0; mt < 2; mt++)
#pragma unroll
            for (int nt = 0; nt < 2; nt++)
#pragma unroll
                for (int i = 0; i < 4; i++) acc[mt][nt][i] = 0.0f;

        // prefetch h chunk 0 (64 rows x 64 k)
        {
            unsigned* A = As0;
#pragma unroll
            for (int it = 0; it < 4; it++) {
                int i  = tid + it * 256;
                int m  = i >> 4;
                int kq = (i & 15) * 4;
                cp16(&A[m * AS_STRIDE + kq], hin + (size_t)(bm + m) * LSTMD + kq);
            }
            cp_commit();
        }

        // prefetch gx for step t+1 (hidden under this step's mma)
        float2 gxn[2][2][2];
        {
            int tn = (t + 1 < T_STEPS) ? (t + 1) : t;
            const float* gxp = gates + (size_t)tn * BATCH * GATES_N;
#pragma unroll
            for (int mt = 0; mt < 2; mt++)
#pragma unroll
                for (int nt = 0; nt < 2; nt++) {
                    int row = gx_row0 + mt * 16;
                    int col = gx_col0 + nt * 8;
                    gxn[mt][nt][0] = *reinterpret_cast<const float2*>(
                        gxp + (size_t)row * GATES_N + col);
                    gxn[mt][nt][1] = *reinterpret_cast<const float2*>(
                        gxp + (size_t)(row + 8) * GATES_N + col);
                }
        }

        for (int c = 0; c < 8; c++) {
            if (c < 7) {
                unsigned* A = As0 + ((c + 1) & 1) * AS_ELEMS;
                int kb = (c + 1) * 64;
#pragma unroll
                for (int it = 0; it < 4; it++) {
                    int i  = tid + it * 256;
                    int m  = i >> 4;
                    int kq = (i & 15) * 4;
                    cp16(&A[m * AS_STRIDE + kq],
                         hin + (size_t)(bm + m) * LSTMD + kb + kq);
                }
                cp_commit();
                cp_wait<1>();
            } else {
                cp_wait<0>();
            }
            __syncthreads();

            const uint32_t abuf  = as_base + (uint32_t)((c & 1) * AS_ELEMS * 4);
            const int      kbase = c * 64;
#pragma unroll
            for (int kk = 0; kk < 64; kk += 8) {
                unsigned af0[4], af1[4], bf[4];
                ldsm4(af0, abuf + a_rel[0] + kk * 4);
                ldsm4(af1, abuf + a_rel[1] + kk * 4);
                ldsm4(bf,  b_base + (uint32_t)((kbase + kk) * 4));
                mma_tf32(acc[0][0], af0[0], af0[1], af0[2], af0[3], bf[0], bf[1]);
                mma_tf32(acc[0][1], af0[0], af0[1], af0[2], af0[3], bf[2], bf[3]);
                mma_tf32(acc[1][0], af1[0], af1[1], af1[2], af1[3], bf[0], bf[1]);
                mma_tf32(acc[1][1], af1[0], af1[1], af1[2], af1[3], bf[2], bf[3]);
            }
            __syncthreads();
        }

        // epilogue: gates + cell update (fast transcendentals)
        float* yst = ys + (size_t)t * BATCH * LSTMD;
#pragma unroll
        for (int mt = 0; mt < 2; mt++) {
#pragma unroll
            for (int nt = 0; nt < 2; nt++) {
                int lrow = wm + mt * 16 + r;
                int lcol = wn + nt * 8 + 2 * q;
                float z00 = acc[mt][nt][0] + gxc[mt][nt][0].x;
                float z01 = acc[mt][nt][1] + gxc[mt][nt][0].y;
                float z10 = acc[mt][nt][2] + gxc[mt][nt][1].x;
                float z11 = acc[mt][nt][3] + gxc[mt][nt][1].y;

                float u0a = (p == 0) ? fast_sigm(z00) : fast_tanh(z00);
                float u1a = fast_sigm(z01);
                float u0b = (p == 0) ? fast_sigm(z10) : fast_tanh(z10);
                float u1b = fast_sigm(z11);

                float v0a = __shfl_xor_sync(0xffffffffu, u0a, 1);
                float v1a = __shfl_xor_sync(0xffffffffu, u1a, 1);
                float v0b = __shfl_xor_sync(0xffffffffu, u0b, 1);
                float v1b = __shfl_xor_sync(0xffffffffu, u1b, 1);

                if (p == 0) {
                    int jl = lcol >> 2;
                    int jg = jt * 16 + jl;
                    {
                        float co = Cs[lrow * CS_STRIDE + jl];
                        float cn = u1a * co + u0a * v0a;
                        Cs[lrow * CS_STRIDE + jl] = cn;
                        float h = v1a * fast_tanh(cn);
                        size_t gi = (size_t)(bm + lrow) * LSTMD + jg;
                        yst[gi]  = h;
                        hout[gi] = __uint_as_float(f2tf32(h));
                    }
                    {
                        int lr2 = lrow + 8;
                        float co = Cs[lr2 * CS_STRIDE + jl];
                        float cn = u1b * co + u0b * v0b;
                        Cs[lr2 * CS_STRIDE + jl] = cn;
                        float h = v1b * fast_tanh(cn);
                        size_t gi = (size_t)(bm + lr2) * LSTMD + jg;
                        yst[gi]  = h;
                        hout[gi] = __uint_as_float(f2tf32(h));
                    }
                }
            }
        }

        // carry prefetched gx
#pragma unroll
        for (int mt = 0; mt < 2; mt++)
#pragma unroll
            for (int nt = 0; nt < 2; nt++) {
                gxc[mt][nt][0] = gxn[mt][nt][0];
                gxc[mt][nt][1] = gxn[mt][nt][1];
            }

        if (t + 1 < T_STEPS) {
            __syncthreads();
            if (tid == 0) {
                __threadfence();
                atomicAdd(mybar, 1u);
                unsigned tgt = (unsigned)(t + 1) * GRP_BLKS;
                unsigned v;
                for (;;) {
                    asm volatile("ld.acquire.gpu.u32 %0, [%1];"
                                 : "=r"(v) : "l"(mybar) : "memory");
                    if (v >= tgt) break;
                    __nanosleep(32);
                }
            }
            __syncthreads();
        }
    }
}

// ---------------- heads as tf32 mma GEMM ------------------------------------
__global__ void __launch_bounds__(256)
heads_mma(const float* __restrict__ Whd,    // [512][64] tf32-rounded
          const float* __restrict__ bmu,
          const float* __restrict__ logstd,
          const float* __restrict__ bv,
          float* __restrict__ out)
{
    __shared__ unsigned As[128][36];
    __shared__ unsigned Bs[32][72];

    const int bm = blockIdx.x * 128;
    const int tid  = threadIdx.x;
    const int warp = tid >> 5;
    const int lane = tid & 31;
    const int wm = (warp & 1) * 64;
    const int wn = (warp >> 1) * 16;
    const int r  = lane >> 2;
    const int q  = lane & 3;

    float acc[4][2][4];
#pragma unroll
    for (int mt = 0; mt < 4; mt++)
#pragma unroll
        for (int nt = 0; nt < 2; nt++)
#pragma unroll
            for (int i = 0; i < 4; i++) acc[mt][nt][i] = 0.0f;

    const float* Ab = g_ys + (size_t)bm * LSTMD;

    for (int k0 = 0; k0 < LSTMD; k0 += 32) {
#pragma unroll
        for (int it = 0; it < 4; it++) {             // A 128x32, cvt to tf32
            int i  = tid + it * 256;
            int m  = i >> 3;
            int kq = (i & 7) * 4;
            float4 v = *reinterpret_cast<const float4*>(
                Ab + (size_t)m * LSTMD + k0 + kq);
            unsigned* d = &As[m][kq];
            d[0] = f2tf32(v.x); d[1] = f2tf32(v.y);
            d[2] = f2tf32(v.z); d[3] = f2tf32(v.w);
        }
#pragma unroll
        for (int it = 0; it < 2; it++) {             // B 32x64 (already rounded)
            int i  = tid + it * 256;
            int kr = i >> 4;
            int nq = (i & 15) * 4;
            uint4 v = *reinterpret_cast<const uint4*>(
                Whd + (size_t)(k0 + kr) * 64 + nq);
            *reinterpret_cast<uint4*>(&Bs[kr][nq]) = v;
        }
        __syncthreads();

#pragma unroll
        for (int kk = 0; kk < 32; kk += 8) {
            unsigned af[4][4], bf[2][2];
#pragma unroll
            for (int mt = 0; mt < 4; mt++) {
                int mb = wm + mt * 16;
                af[mt][0] = As[mb + r    ][kk + q];
                af[mt][1] = As[mb + r + 8][kk + q];
                af[mt][2] = As[mb + r    ][kk + q + 4];
                af[mt][3] = As[mb + r + 8][kk + q + 4];
            }
#pragma unroll
            for (int nt = 0; nt < 2; nt++) {
                int nb = wn + nt * 8 + r;
                bf[nt][0] = Bs[kk + q    ][nb];
                bf[nt][1] = Bs[kk + q + 4][nb];
            }
#pragma unroll
            for (int mt = 0; mt < 4; mt++)
#pragma unroll
                for (int nt = 0; nt < 2; nt++)
                    mma_tf32(acc[mt][nt], af[mt][0], af[mt][1], af[mt][2], af[mt][3],
                             bf[nt][0], bf[nt][1]);
        }
        __syncthreads();
    }

    float* mu    = out;
    float* sigma = out + (size_t)ROWS * ACTD;
    float* value = out + (size_t)2 * ROWS * ACTD;

#pragma unroll
    for (int mt = 0; mt < 4; mt++) {
#pragma unroll
        for (int nt = 0; nt < 2; nt++) {
            int row = bm + wm + mt * 16 + r;
            int col = wn + nt * 8 + 2 * q;
            if (col < 32) {
                float b0 = bmu[col], b1 = bmu[col + 1];
                float s0 = expf(logstd[col]), s1 = expf(logstd[col + 1]);
                mu[(size_t)row * ACTD + col]           = acc[mt][nt][0] + b0;
                mu[(size_t)row * ACTD + col + 1]       = acc[mt][nt][1] + b1;
                mu[(size_t)(row + 8) * ACTD + col]     = acc[mt][nt][2] + b0;
                mu[(size_t)(row + 8) * ACTD + col + 1] = acc[mt][nt][3] + b1;
                sigma[(size_t)row * ACTD + col]           = s0;
                sigma[(size_t)row * ACTD + col + 1]       = s1;
                sigma[(size_t)(row + 8) * ACTD + col]     = s0;
                sigma[(size_t)(row + 8) * ACTD + col + 1] = s1;
            } else if (col == 32) {
                value[row]     = acc[mt][nt][0] + bv[0];
                value[row + 8] = acc[mt][nt][2] + bv[0];
            }
        }
    }
}

// ---------------- launch ----------------------------------------------------
extern "C" void kernel_launch(void* const* d_in, const int* in_sizes, int n_in,
                              void* d_out, int out_size)
{
    (void)in_sizes; (void)n_in; (void)out_size;
    const float* x      = (const float*)d_in[0];
    const float* W_enc  = (const float*)d_in[1];
    const float* b_enc  = (const float*)d_in[2];
    const float* W_i    = (const float*)d_in[3];
    const float* W_h    = (const float*)d_in[4];
    const float* b_lstm = (const float*)d_in[5];
    const float* W_mu   = (const float*)d_in[6];
    const float* b_mu   = (const float*)d_in[7];
    const float* logstd = (const float*)d_in[8];
    const float* W_v    = (const float*)d_in[9];
    const float* b_v    = (const float*)d_in[10];
    float* out = (float*)d_out;

    float *xr, *WencR, *feats, *gates, *ys, *hT, *WiP, *bP, *Whd;
    unsigned* WhP;
    cudaGetSymbolAddress((void**)&xr,    g_xr);
    cudaGetSymbolAddress((void**)&WencR, g_WencR);
    cudaGetSymbolAddress((void**)&feats, g_feats);
    cudaGetSymbolAddress((void**)&gates, g_gates);
    cudaGetSymbolAddress((void**)&ys,    g_ys);
    cudaGetSymbolAddress((void**)&hT,    g_hT);
    cudaGetSymbolAddress((void**)&WiP,   g_WiP);
    cudaGetSymbolAddress((void**)&WhP,   g_WhP);
    cudaGetSymbolAddress((void**)&bP,    g_bP);
    cudaGetSymbolAddress((void**)&Whd,   g_Whd);

    static int attr_set = 0;
    if (!attr_set) {
        cudaFuncSetAttribute(lstm_persistent,
                             cudaFuncAttributeMaxDynamicSharedMemorySize, SMEM_LSTM);
        cudaFuncSetAttribute(gemm_mma,
                             cudaFuncAttributeMaxDynamicSharedMemorySize, SMEM_GEMM);
        attr_set = 1;
    }

    zero_kernel<<<(HT_ELEMS + 255) / 256, 256>>>(hT, HT_ELEMS);
    zero_bar4<<<1, 128>>>();

    round4_kernel<<<(ROWS * OBSD / 4 + 255) / 256, 256>>>(
        (const float4*)x, (float4*)xr, ROWS * OBSD / 4);
    round4_kernel<<<(OBSD * HIDD / 4 + 255) / 256, 256>>>(
        (const float4*)W_enc, (float4*)WencR, OBSD * HIDD / 4);
    permute_wi<<<(HIDD * GATES_N) / 256, 256>>>(W_i, WiP);
    permute_wh<<<(LSTMD * GATES_N) / 256, 256>>>(W_h, WhP);
    permute_b<<<(GATES_N + 255) / 256, 256>>>(b_lstm, bP);
    prep_whd<<<(LSTMD * 64) / 256, 256>>>(W_mu, W_v, Whd);

    {
        dim3 grid(HIDD / 128, ROWS / 128);
        gemm_mma<<<grid, 256, SMEM_GEMM>>>(xr, WencR, b_enc, feats,
                                           ROWS, HIDD, OBSD, 1, 1);
    }
    {
        dim3 grid(GATES_N / 128, ROWS / 128);
        gemm_mma<<<grid, 256, SMEM_GEMM>>>(feats, WiP, bP, gates,
                                           ROWS, GATES_N, HIDD, 0, 0);
    }
    {
        dim3 grid(32, 4);
        lstm_persistent<<<grid, 256, SMEM_LSTM>>>(WhP, gates, ys);
    }
    heads_mma<<<ROWS / 128, 256>>>(Whd, b_mu, logstd, b_v, out);
}

// round 17
// speedup vs baseline: 1.6923x; 1.6100x over previous
#include <cuda_runtime.h>
#include <cuda_fp16.h>
#include <math.h>
#include <stdint.h>

#define T_STEPS 512
#define BATCH   256
#define OBSD    256
#define HIDD    512
#define LSTMD   512
#define ACTD    32
#define ROWS    (T_STEPS * BATCH)   /* 131072 */
#define GATES_N (4 * LSTMD)         /* 2048 */
#define HT_ELEMS (BATCH * LSTMD)    /* 131072 */
#define NGRP     4
#define GRP_BLKS 32

// one extern-shared symbol for all dynamic-smem kernels
extern __shared__ char dynsmem[];

// ---------------- scratch (static device globals) ---------------------------
__device__ __half  g_xh   [(size_t)ROWS * OBSD];          // x as fp16
__device__ __half  g_featsH[(size_t)ROWS * HIDD];         // encoder out (fp16)
__device__ float   g_gates[(size_t)ROWS * GATES_N];       // fp32, permuted 4j+g
__device__ __half  g_ys   [(size_t)ROWS * LSTMD];         // h history (fp16) = ys
__device__ __half  g_h0   [HT_ELEMS];                     // zero h for t=0
__device__ __half  g_WencT[(size_t)HIDD * OBSD];          // W_enc^T [n][k]
__device__ __half  g_WiT  [(size_t)GATES_N * HIDD];       // permuted W_i^T [c][k]
__device__ __half  g_WhT  [(size_t)GATES_N * HIDD];       // permuted W_h^T [c][k]
__device__ __half  g_WhdT [(size_t)64 * LSTMD];           // heads W^T [n][k]
__device__ float   g_bP   [GATES_N];                      // permuted b_lstm
__device__ unsigned g_bar4[NGRP * 32];

// fast transcendentals (~1e-6 rel err)
__device__ __forceinline__ float fast_tanh(float x) {
    float e = __expf(2.0f * x);
    return 1.0f - __fdividef(2.0f, e + 1.0f);
}
__device__ __forceinline__ float fast_sigm(float x) {
    return __fdividef(1.0f, 1.0f + __expf(-x));
}
__device__ __forceinline__ float gelu_f(float x) {
    float x3 = x * x * x;
    float t  = fast_tanh(0.7978845608028654f * (x + 0.044715f * x3));
    return 0.5f * x * (1.0f + t);
}

__device__ __forceinline__ void mma_f16(float c[4],
                                        unsigned a0, unsigned a1, unsigned a2, unsigned a3,
                                        unsigned b0, unsigned b1) {
    asm volatile(
        "mma.sync.aligned.m16n8k16.row.col.f32.f16.f16.f32 "
        "{%0,%1,%2,%3}, {%4,%5,%6,%7}, {%8,%9}, {%0,%1,%2,%3};\n"
        : "+f"(c[0]), "+f"(c[1]), "+f"(c[2]), "+f"(c[3])
        : "r"(a0), "r"(a1), "r"(a2), "r"(a3), "r"(b0), "r"(b1));
}

__device__ __forceinline__ void ldsm4(unsigned f[4], uint32_t addr) {
    asm volatile("ldmatrix.sync.aligned.m8n8.x4.shared.b16 {%0,%1,%2,%3}, [%4];"
                 : "=r"(f[0]), "=r"(f[1]), "=r"(f[2]), "=r"(f[3]) : "r"(addr));
}

__device__ __forceinline__ void cp16(void* smem_dst, const void* gsrc) {
    unsigned d = (unsigned)__cvta_generic_to_shared(smem_dst);
    asm volatile("cp.async.ca.shared.global [%0], [%1], 16;\n" :: "r"(d), "l"(gsrc));
}
__device__ __forceinline__ void cp_commit() {
    asm volatile("cp.async.commit_group;\n");
}
template <int N>
__device__ __forceinline__ void cp_wait() {
    asm volatile("cp.async.wait_group %0;\n" :: "n"(N));
}

// ---------------- small utility kernels -------------------------------------
__global__ void zero_u32(unsigned* p, int n) {
    int i = blockIdx.x * blockDim.x + threadIdx.x;
    if (i < n) p[i] = 0u;
}
__global__ void zero_bar4() {
    if (threadIdx.x < NGRP * 32) g_bar4[threadIdx.x] = 0u;
}

// x (float4) -> half pairs
__global__ void cvt_half(const float4* __restrict__ in, __half2* __restrict__ out, int n4) {
    int i = blockIdx.x * blockDim.x + threadIdx.x;
    if (i < n4) {
        float4 v = in[i];
        out[2 * i]     = __floats2half2_rn(v.x, v.y);
        out[2 * i + 1] = __floats2half2_rn(v.z, v.w);
    }
}
// W_enc [256][512] -> WT[n][k] half
__global__ void prep_wenc(const float* __restrict__ W, __half* __restrict__ WT) {
    int idx = blockIdx.x * 256 + threadIdx.x;       // < 512*256
    int n = idx >> 8, k = idx & 255;
    WT[idx] = __float2half_rn(W[(size_t)k * HIDD + n]);
}
// W [512][2048] -> WT[c][k] half, c = 4j+g permuted
__global__ void prep_w_perm_t(const float* __restrict__ W, __half* __restrict__ WT) {
    int idx = blockIdx.x * 256 + threadIdx.x;       // < 2048*512
    int c = idx >> 9, k = idx & 511;
    WT[idx] = __float2half_rn(W[(size_t)k * GATES_N + (c & 3) * LSTMD + (c >> 2)]);
}
__global__ void permute_b(const float* __restrict__ b, float* __restrict__ bp) {
    int idx = blockIdx.x * 256 + threadIdx.x;
    if (idx < GATES_N) bp[idx] = b[(idx & 3) * LSTMD + (idx >> 2)];
}
// heads W^T [n][k]: n<32 -> W_mu[k][n], n==32 -> W_v[k], else 0
__global__ void prep_whd(const float* __restrict__ Wmu,
                         const float* __restrict__ Wv,
                         __half* __restrict__ WT) {
    int idx = blockIdx.x * 256 + threadIdx.x;       // < 64*512
    int n = idx >> 9, k = idx & 511;
    float v = 0.0f;
    if (n < 32)       v = Wmu[k * ACTD + n];
    else if (n == 32) v = Wv[k];
    WT[idx] = __float2half_rn(v);
}

// ---------------- fp16 GEMM: C = act(A[M,K] @ BT[N,K]^T + bias) -------------
// 128x128 tiles, BK=32, double-buffered cp.async, ldmatrix everywhere.
#define GH_STRIDE 40                            /* halves; 80B rows */
#define GH_A_ELEMS (128 * GH_STRIDE)            /* per buf, halves */
#define GH_B_ELEMS (128 * GH_STRIDE)
#define SMEM_GEMMH ((2 * GH_A_ELEMS + 2 * GH_B_ELEMS) * 2)

__global__ void __launch_bounds__(256)
gemm_h(const __half* __restrict__ A, const __half* __restrict__ BT,
       const float* __restrict__ bias, void* __restrict__ Cout,
       int M, int N, int K, int do_gelu, int half_out)
{
    __half* As = (__half*)dynsmem;                       // [2][128][40]
    __half* Bs = As + 2 * GH_A_ELEMS;                    // [2][128][40]

    const int bm = blockIdx.y * 128;
    const int bn = blockIdx.x * 128;
    const int tid  = threadIdx.x;
    const int warp = tid >> 5;
    const int lane = tid & 31;
    const int wm = (warp & 1) * 64;
    const int wn = (warp >> 1) * 32;
    const int r  = lane >> 2;
    const int q  = lane & 3;

    float acc[4][4][4];
#pragma unroll
    for (int mt = 0; mt < 4; mt++)
#pragma unroll
        for (int nt = 0; nt < 4; nt++)
#pragma unroll
            for (int i = 0; i < 4; i++) acc[mt][nt][i] = 0.0f;

    const int nK = K >> 5;

    auto load_stage = [&](int kt, int buf) {
        __half* Ad = As + buf * GH_A_ELEMS;
        __half* Bd = Bs + buf * GH_B_ELEMS;
        int k0 = kt * 32;
#pragma unroll
        for (int it = 0; it < 2; it++) {
            int i   = tid + it * 256;       // 0..511
            int row = i >> 2;
            int c4  = i & 3;
            cp16(&Ad[row * GH_STRIDE + c4 * 8],
                 A + (size_t)(bm + row) * K + k0 + c4 * 8);
        }
#pragma unroll
        for (int it = 0; it < 2; it++) {
            int i   = tid + it * 256;
            int row = i >> 2;
            int c4  = i & 3;
            cp16(&Bd[row * GH_STRIDE + c4 * 8],
                 BT + (size_t)(bn + row) * K + k0 + c4 * 8);
        }
        cp_commit();
    };

    // ldmatrix byte addresses
    const uint32_t sm0 = (uint32_t)__cvta_generic_to_shared(dynsmem);
    uint32_t a_rel[4], b_rel[2];
#pragma unroll
    for (int mt = 0; mt < 4; mt++)
        a_rel[mt] = (uint32_t)(((wm + mt * 16 + (lane & 15)) * GH_STRIDE
                                + (lane >> 4) * 8) * 2);
#pragma unroll
    for (int nt2 = 0; nt2 < 2; nt2++)
        b_rel[nt2] = (uint32_t)(((wn + nt2 * 16 + (lane & 7) + ((lane >> 3) & 1) * 8)
                                 * GH_STRIDE + (lane >> 4) * 8) * 2);
    const uint32_t b_off0 = sm0 + 2 * GH_A_ELEMS * 2;

    load_stage(0, 0);

    for (int kt = 0; kt < nK; kt++) {
        if (kt + 1 < nK) { load_stage(kt + 1, (kt + 1) & 1); cp_wait<1>(); }
        else             { cp_wait<0>(); }
        __syncthreads();

        const uint32_t abuf = sm0 + (uint32_t)((kt & 1) * GH_A_ELEMS * 2);
        const uint32_t bbuf = b_off0 + (uint32_t)((kt & 1) * GH_B_ELEMS * 2);
#pragma unroll
        for (int ks = 0; ks < 2; ks++) {       // k = ks*16
            unsigned af[4][4], bfr[2][4];
#pragma unroll
            for (int mt = 0; mt < 4; mt++) ldsm4(af[mt], abuf + a_rel[mt] + ks * 32);
#pragma unroll
            for (int nt2 = 0; nt2 < 2; nt2++) ldsm4(bfr[nt2], bbuf + b_rel[nt2] + ks * 32);
#pragma unroll
            for (int mt = 0; mt < 4; mt++)
#pragma unroll
                for (int nt2 = 0; nt2 < 2; nt2++) {
                    mma_f16(acc[mt][2 * nt2 + 0], af[mt][0], af[mt][1], af[mt][2], af[mt][3],
                            bfr[nt2][0], bfr[nt2][2]);
                    mma_f16(acc[mt][2 * nt2 + 1], af[mt][0], af[mt][1], af[mt][2], af[mt][3],
                            bfr[nt2][1], bfr[nt2][3]);
                }
        }
        __syncthreads();
    }

#pragma unroll
    for (int mt = 0; mt < 4; mt++) {
#pragma unroll
        for (int nt = 0; nt < 4; nt++) {
            int row = bm + wm + mt * 16 + r;
            int col = bn + wn + nt * 8 + 2 * q;
            float b0 = bias[col], b1 = bias[col + 1];
            float z00 = acc[mt][nt][0] + b0, z01 = acc[mt][nt][1] + b1;
            float z10 = acc[mt][nt][2] + b0, z11 = acc[mt][nt][3] + b1;
            if (do_gelu) {
                z00 = gelu_f(z00); z01 = gelu_f(z01);
                z10 = gelu_f(z10); z11 = gelu_f(z11);
            }
            if (half_out) {
                __half2* C = (__half2*)Cout;
                C[((size_t)row * N + col) >> 1]       = __floats2half2_rn(z00, z01);
                C[((size_t)(row + 8) * N + col) >> 1] = __floats2half2_rn(z10, z11);
            } else {
                float* C = (float*)Cout;
                *reinterpret_cast<float2*>(C + (size_t)row * N + col) =
                    make_float2(z00, z01);
                *reinterpret_cast<float2*>(C + (size_t)(row + 8) * N + col) =
                    make_float2(z10, z11);
            }
        }
    }
}

// ---------------- persistent fused LSTM recurrence (fp16 mma) ---------------
// 128 blocks (32 j x 4 b). h history lives in g_ys (fp16) — no separate hT.
#define WH_STRIDE 520                           /* halves; 1040B rows */
#define WH_ELEMS  (64 * WH_STRIDE)              /* halves */
#define AH_STRIDE 72                            /* halves; 144B rows */
#define AH_ELEMS  (64 * AH_STRIDE)              /* per buf */
#define CS_STRIDE 17
#define SMEM_LSTM ((WH_ELEMS + 2 * AH_ELEMS) * 2 + 64 * CS_STRIDE * 4)

__global__ void __launch_bounds__(256, 1)
lstm_persistent(const __half* __restrict__ WhT,
                const float* __restrict__ gates,
                __half* __restrict__ ys)
{
    __half* Wst = (__half*)dynsmem;                      // [64][520]  (n, k)
    __half* As0 = Wst + WH_ELEMS;                        // [2][64][72] (m, k)
    float*  Cs  = (float*)(As0 + 2 * AH_ELEMS);          // [64][17]

    const int jt = blockIdx.x;
    const int bt = blockIdx.y;
    const int bn = jt * 64;
    const int bm = bt * 64;
    const int tid  = threadIdx.x;
    const int warp = tid >> 5;
    const int lane = tid & 31;
    const int wm = (warp & 1) * 32;
    const int wn = (warp >> 1) * 16;
    const int r  = lane >> 2;
    const int q  = lane & 3;
    const int p  = q & 1;
    unsigned* mybar = &g_bar4[bt * 32];

    // W tile: rows bn..bn+63 of WhT [c][k=512] half
    for (int i = tid; i < 64 * 64; i += 256) {
        int n = i >> 6, c16 = i & 63;
        *reinterpret_cast<uint4*>(&Wst[n * WH_STRIDE + c16 * 8]) =
            *reinterpret_cast<const uint4*>(WhT + (size_t)(bn + n) * HIDD + c16 * 8);
    }
    for (int i = tid; i < 64 * CS_STRIDE; i += 256) Cs[i] = 0.0f;
    __syncthreads();

    // ldmatrix byte addresses
    const uint32_t sm0 = (uint32_t)__cvta_generic_to_shared(dynsmem);
    const uint32_t as_base = sm0 + WH_ELEMS * 2;
    uint32_t a_rel[2];
#pragma unroll
    for (int mt = 0; mt < 2; mt++)
        a_rel[mt] = (uint32_t)(((wm + mt * 16 + (lane & 15)) * AH_STRIDE
                                + (lane >> 4) * 8) * 2);
    const uint32_t b_base = sm0 +
        (uint32_t)(((wn + (lane & 7) + ((lane >> 3) & 1) * 8) * WH_STRIDE
                    + (lane >> 4) * 8) * 2);

    const int gx_row0 = bm + wm + r;
    const int gx_col0 = bn + wn + 2 * q;

    // preload gx for t=0
    float2 gxc[2][2][2];
#pragma unroll
    for (int mt = 0; mt < 2; mt++)
#pragma unroll
        for (int nt = 0; nt < 2; nt++) {
            int row = gx_row0 + mt * 16;
            int col = gx_col0 + nt * 8;
            gxc[mt][nt][0] = *reinterpret_cast<const float2*>(
                gates + (size_t)row * GATES_N + col);
            gxc[mt][nt][1] = *reinterpret_cast<const float2*>(
                gates + (size_t)(row + 8) * GATES_N + col);
        }

    for (int t = 0; t < T_STEPS; t++) {
        const __half* hin = (t == 0) ? g_h0
                                     : ys + (size_t)(t - 1) * BATCH * LSTMD;
        __half* yst = ys + (size_t)t * BATCH * LSTMD;

        float acc[2][2][4];
#pragma unroll
        for (int mt = 0; mt < 2; mt++)
#pragma unroll
            for (int nt = 0; nt < 2; nt++)
#pragma unroll
                for (int i = 0; i < 4; i++) acc[mt][nt][i] = 0.0f;

        // prefetch h chunk 0 (64 rows x 64 k halves = 128B/row)
        {
            __half* A = As0;
#pragma unroll
            for (int it = 0; it < 2; it++) {
                int i  = tid + it * 256;       // 0..511
                int m  = i >> 3;
                int c8 = i & 7;
                cp16(&A[m * AH_STRIDE + c8 * 8],
                     hin + (size_t)(bm + m) * LSTMD + c8 * 8);
            }
            cp_commit();
        }

        // prefetch gx for step t+1 (hidden under this step's mma)
        float2 gxn[2][2][2];
        {
            int tn = (t + 1 < T_STEPS) ? (t + 1) : t;
            const float* gxp = gates + (size_t)tn * BATCH * GATES_N;
#pragma unroll
            for (int mt = 0; mt < 2; mt++)
#pragma unroll
                for (int nt = 0; nt < 2; nt++) {
                    int row = gx_row0 + mt * 16;
                    int col = gx_col0 + nt * 8;
                    gxn[mt][nt][0] = *reinterpret_cast<const float2*>(
                        gxp + (size_t)row * GATES_N + col);
                    gxn[mt][nt][1] = *reinterpret_cast<const float2*>(
                        gxp + (size_t)(row + 8) * GATES_N + col);
                }
        }

        for (int c = 0; c < 8; c++) {
            if (c < 7) {
                __half* A = As0 + ((c + 1) & 1) * AH_ELEMS;
                int kb = (c + 1) * 64;
#pragma unroll
                for (int it = 0; it < 2; it++) {
                    int i  = tid + it * 256;
                    int m  = i >> 3;
                    int c8 = i & 7;
                    cp16(&A[m * AH_STRIDE + c8 * 8],
                         hin + (size_t)(bm + m) * LSTMD + kb + c8 * 8);
                }
                cp_commit();
                cp_wait<1>();
            } else {
                cp_wait<0>();
            }
            __syncthreads();

            const uint32_t abuf  = as_base + (uint32_t)((c & 1) * AH_ELEMS * 2);
            const int      kbase = c * 64;         // halves
#pragma unroll
            for (int ks = 0; ks < 4; ks++) {       // k = ks*16 within chunk
                unsigned af0[4], af1[4], bf[4];
                ldsm4(af0, abuf + a_rel[0] + ks * 32);
                ldsm4(af1, abuf + a_rel[1] + ks * 32);
                ldsm4(bf,  b_base + (uint32_t)((kbase + ks * 16) * 2));
                mma_f16(acc[0][0], af0[0], af0[1], af0[2], af0[3], bf[0], bf[2]);
                mma_f16(acc[0][1], af0[0], af0[1], af0[2], af0[3], bf[1], bf[3]);
                mma_f16(acc[1][0], af1[0], af1[1], af1[2], af1[3], bf[0], bf[2]);
                mma_f16(acc[1][1], af1[0], af1[1], af1[2], af1[3], bf[1], bf[3]);
            }
            __syncthreads();
        }

        // epilogue: gates + cell update; write h (fp16) into ys[t]
#pragma unroll
        for (int mt = 0; mt < 2; mt++) {
#pragma unroll
            for (int nt = 0; nt < 2; nt++) {
                int lrow = wm + mt * 16 + r;
                int lcol = wn + nt * 8 + 2 * q;
                float z00 = acc[mt][nt][0] + gxc[mt][nt][0].x;
                float z01 = acc[mt][nt][1] + gxc[mt][nt][0].y;
                float z10 = acc[mt][nt][2] + gxc[mt][nt][1].x;
                float z11 = acc[mt][nt][3] + gxc[mt][nt][1].y;

                float u0a = (p == 0) ? fast_sigm(z00) : fast_tanh(z00);
                float u1a = fast_sigm(z01);
                float u0b = (p == 0) ? fast_sigm(z10) : fast_tanh(z10);
                float u1b = fast_sigm(z11);

                float v0a = __shfl_xor_sync(0xffffffffu, u0a, 1);
                float v1a = __shfl_xor_sync(0xffffffffu, u1a, 1);
                float v0b = __shfl_xor_sync(0xffffffffu, u0b, 1);
                float v1b = __shfl_xor_sync(0xffffffffu, u1b, 1);

                if (p == 0) {
                    int jl = lcol >> 2;
                    int jg = jt * 16 + jl;
                    {
                        float co = Cs[lrow * CS_STRIDE + jl];
                        float cn = u1a * co + u0a * v0a;
                        Cs[lrow * CS_STRIDE + jl] = cn;
                        float h = v1a * fast_tanh(cn);
                        yst[(size_t)(bm + lrow) * LSTMD + jg] = __float2half_rn(h);
                    }
                    {
                        int lr2 = lrow + 8;
                        float co = Cs[lr2 * CS_STRIDE + jl];
                        float cn = u1b * co + u0b * v0b;
                        Cs[lr2 * CS_STRIDE + jl] = cn;
                        float h = v1b * fast_tanh(cn);
                        yst[(size_t)(bm + lr2) * LSTMD + jg] = __float2half_rn(h);
                    }
                }
            }
        }

        // carry prefetched gx
#pragma unroll
        for (int mt = 0; mt < 2; mt++)
#pragma unroll
            for (int nt = 0; nt < 2; nt++) {
                gxc[mt][nt][0] = gxn[mt][nt][0];
                gxc[mt][nt][1] = gxn[mt][nt][1];
            }

        if (t + 1 < T_STEPS) {
            __syncthreads();
            if (tid == 0) {
                __threadfence();
                atomicAdd(mybar, 1u);
                unsigned tgt = (unsigned)(t + 1) * GRP_BLKS;
                unsigned v;
                for (;;) {
                    asm volatile("ld.acquire.gpu.u32 %0, [%1];"
                                 : "=r"(v) : "l"(mybar) : "memory");
                    if (v >= tgt) break;
                    __nanosleep(32);
                }
            }
            __syncthreads();
        }
    }
}

// ---------------- heads: fp16 mma GEMM over ys ------------------------------
// 128m x 64n tiles, K=512, single-buffered cp.async.
__global__ void __launch_bounds__(256)
heads_mma(const __half* __restrict__ WhdT,   // [64][512] half
          const float* __restrict__ bmu,
          const float* __restrict__ logstd,
          const float* __restrict__ bv,
          float* __restrict__ out)
{
    __shared__ __half As[128 * GH_STRIDE];   // [128][40]
    __shared__ __half Bs[64 * GH_STRIDE];    // [64][40]

    const int bm = blockIdx.x * 128;
    const int tid  = threadIdx.x;
    const int warp = tid >> 5;
    const int lane = tid & 31;
    const int wm = (warp & 1) * 64;
    const int wn = (warp >> 1) * 16;
    const int r  = lane >> 2;
    const int q  = lane & 3;

    float acc[4][2][4];
#pragma unroll
    for (int mt = 0; mt < 4; mt++)
#pragma unroll
        for (int nt = 0; nt < 2; nt++)
#pragma unroll
            for (int i = 0; i < 4; i++) acc[mt][nt][i] = 0.0f;

    const __half* Ab = g_ys + (size_t)bm * LSTMD;

    const uint32_t a0 = (uint32_t)__cvta_generic_to_shared(As);
    const uint32_t b0 = (uint32_t)__cvta_generic_to_shared(Bs);
    uint32_t a_rel[4];
#pragma unroll
    for (int mt = 0; mt < 4; mt++)
        a_rel[mt] = a0 + (uint32_t)(((wm + mt * 16 + (lane & 15)) * GH_STRIDE
                                     + (lane >> 4) * 8) * 2);
    const uint32_t b_rel = b0 +
        (uint32_t)(((wn + (lane & 7) + ((lane >> 3) & 1) * 8) * GH_STRIDE
                    + (lane >> 4) * 8) * 2);

    for (int k0 = 0; k0 < LSTMD; k0 += 32) {
#pragma unroll
        for (int it = 0; it < 2; it++) {             // A 128x32
            int i   = tid + it * 256;
            int row = i >> 2;
            int c4  = i & 3;
            cp16(&As[row * GH_STRIDE + c4 * 8],
                 Ab + (size_t)row * LSTMD + k0 + c4 * 8);
        }
        {                                            // B 64x32 (256 cp16)
            int row = tid >> 2;
            int c4  = tid & 3;
            cp16(&Bs[row * GH_STRIDE + c4 * 8],
                 WhdT + (size_t)row * LSTMD + k0 + c4 * 8);
        }
        cp_commit();
        cp_wait<0>();
        __syncthreads();

#pragma unroll
        for (int ks = 0; ks < 2; ks++) {
            unsigned af[4][4], bf[4];
#pragma unroll
            for (int mt = 0; mt < 4; mt++) ldsm4(af[mt], a_rel[mt] + ks * 32);
            ldsm4(bf, b_rel + ks * 32);
#pragma unroll
            for (int mt = 0; mt < 4; mt++) {
                mma_f16(acc[mt][0], af[mt][0], af[mt][1], af[mt][2], af[mt][3],
                        bf[0], bf[2]);
                mma_f16(acc[mt][1], af[mt][0], af[mt][1], af[mt][2], af[mt][3],
                        bf[1], bf[3]);
            }
        }
        __syncthreads();
    }

    float* mu    = out;
    float* sigma = out + (size_t)ROWS * ACTD;
    float* value = out + (size_t)2 * ROWS * ACTD;

#pragma unroll
    for (int mt = 0; mt < 4; mt++) {
#pragma unroll
        for (int nt = 0; nt < 2; nt++) {
            int row = bm + wm + mt * 16 + r;
            int col = wn + nt * 8 + 2 * q;
            if (col < 32) {
                float b0v = bmu[col], b1v = bmu[col + 1];
                float s0 = expf(logstd[col]), s1 = expf(logstd[col + 1]);
                mu[(size_t)row * ACTD + col]           = acc[mt][nt][0] + b0v;
                mu[(size_t)row * ACTD + col + 1]       = acc[mt][nt][1] + b1v;
                mu[(size_t)(row + 8) * ACTD + col]     = acc[mt][nt][2] + b0v;
                mu[(size_t)(row + 8) * ACTD + col + 1] = acc[mt][nt][3] + b1v;
                sigma[(size_t)row * ACTD + col]           = s0;
                sigma[(size_t)row * ACTD + col + 1]       = s1;
                sigma[(size_t)(row + 8) * ACTD + col]     = s0;
                sigma[(size_t)(row + 8) * ACTD + col + 1] = s1;
            } else if (col == 32) {
                value[row]     = acc[mt][nt][0] + bv[0];
                value[row + 8] = acc[mt][nt][2] + bv[0];
            }
        }
    }
}

// ---------------- launch ----------------------------------------------------
extern "C" void kernel_launch(void* const* d_in, const int* in_sizes, int n_in,
                              void* d_out, int out_size)
{
    (void)in_sizes; (void)n_in; (void)out_size;
    const float* x      = (const float*)d_in[0];
    const float* W_enc  = (const float*)d_in[1];
    const float* b_enc  = (const float*)d_in[2];
    const float* W_i    = (const float*)d_in[3];
    const float* W_h    = (const float*)d_in[4];
    const float* b_lstm = (const float*)d_in[5];
    const float* W_mu   = (const float*)d_in[6];
    const float* b_mu   = (const float*)d_in[7];
    const float* logstd = (const float*)d_in[8];
    const float* W_v    = (const float*)d_in[9];
    const float* b_v    = (const float*)d_in[10];
    float* out = (float*)d_out;

    __half *xh, *featsH, *ysH, *h0, *WencT, *WiT, *WhT, *WhdT;
    float *gates, *bP;
    cudaGetSymbolAddress((void**)&xh,     g_xh);
    cudaGetSymbolAddress((void**)&featsH, g_featsH);
    cudaGetSymbolAddress((void**)&gates,  g_gates);
    cudaGetSymbolAddress((void**)&ysH,    g_ys);
    cudaGetSymbolAddress((void**)&h0,     g_h0);
    cudaGetSymbolAddress((void**)&WencT,  g_WencT);
    cudaGetSymbolAddress((void**)&WiT,    g_WiT);
    cudaGetSymbolAddress((void**)&WhT,    g_WhT);
    cudaGetSymbolAddress((void**)&WhdT,   g_WhdT);
    cudaGetSymbolAddress((void**)&bP,     g_bP);

    static int attr_set = 0;
    if (!attr_set) {
        cudaFuncSetAttribute(lstm_persistent,
                             cudaFuncAttributeMaxDynamicSharedMemorySize, SMEM_LSTM);
        cudaFuncSetAttribute(gemm_h,
                             cudaFuncAttributeMaxDynamicSharedMemorySize, SMEM_GEMMH);
        attr_set = 1;
    }

    // zero h0 (fp16 zeros == u32 zeros) + barrier counters
    zero_u32<<<(HT_ELEMS / 2 + 255) / 256, 256>>>((unsigned*)h0, HT_ELEMS / 2);
    zero_bar4<<<1, 128>>>();

    // preprocessing: convert/permute/transpose weights + x to fp16
    cvt_half<<<(ROWS * OBSD / 4 + 255) / 256, 256>>>(
        (const float4*)x, (__half2*)xh, ROWS * OBSD / 4);
    prep_wenc<<<(HIDD * OBSD) / 256, 256>>>(W_enc, WencT);
    prep_w_perm_t<<<(GATES_N * HIDD) / 256, 256>>>(W_i, WiT);
    prep_w_perm_t<<<(GATES_N * HIDD) / 256, 256>>>(W_h, WhT);
    permute_b<<<(GATES_N + 255) / 256, 256>>>(b_lstm, bP);
    prep_whd<<<(64 * LSTMD) / 256, 256>>>(W_mu, W_v, WhdT);

    // encoder: featsH = gelu(xh @ WencT^T + b_enc)   [131072 x 512, K=256]
    {
        dim3 grid(HIDD / 128, ROWS / 128);
        gemm_h<<<grid, 256, SMEM_GEMMH>>>(xh, WencT, b_enc, featsH,
                                          ROWS, HIDD, OBSD, 1, 1);
    }
    // gates = featsH @ WiT^T + bP  (fp32 out)        [131072 x 2048, K=512]
    {
        dim3 grid(GATES_N / 128, ROWS / 128);
        gemm_h<<<grid, 256, SMEM_GEMMH>>>(featsH, WiT, bP, gates,
                                          ROWS, GATES_N, HIDD, 0, 0);
    }
    // recurrence: persistent, h history = ys (fp16)
    {
        dim3 grid(32, 4);
        lstm_persistent<<<grid, 256, SMEM_LSTM>>>(WhT, gates, ysH);
    }
    heads_mma<<<ROWS / 128, 256>>>(WhdT, b_mu, logstd, b_v, out);
}